// round 1
// baseline (speedup 1.0000x reference)
#include <cuda_runtime.h>
#include <math.h>

#define B_  2
#define L_  256
#define DM_ 256
#define H_  8
#define DH_ 32
#define T_  4
#define NK_ 4
#define M_  (DH_*NK_)          // 128 gaussian terms per (h,t)
#define NPAIR ((L_*(L_+1))/2)  // 32896 (i<=j pairs)

// ---------------- scratch (device globals; no allocation allowed) -------------
__device__ float g_WT[4][DM_*DM_];          // WQ^T, WK^T, WV^T, WO^T  (1MB)
__device__ float g_Q[B_*H_*L_*DH_];
__device__ float g_K[B_*H_*L_*DH_];
__device__ float g_V[B_*H_*L_*DH_];
__device__ float g_relP[H_*T_*M_*4];        // packed (mu, A, w, 0)
__device__ float g_absP[H_*T_*M_*4];
__device__ float g_gabs[B_*H_*L_];
__device__ float g_grel[B_*H_*L_*L_];       // 4MB
__device__ float g_outh[B_*L_*DM_];

__device__ __forceinline__ float ex2f(float x){
    float r; asm("ex2.approx.ftz.f32 %0, %1;" : "=f"(r) : "f"(x)); return r;
}

// ---------------- prep: transpose W's + pack gaussian params ------------------
__global__ void prep_kernel(const float* __restrict__ WQ, const float* __restrict__ WK,
                            const float* __restrict__ WV, const float* __restrict__ WO,
                            const float* __restrict__ mu_a, const float* __restrict__ sg_a,
                            const float* __restrict__ w_a,
                            const float* __restrict__ mu_r, const float* __restrict__ sg_r,
                            const float* __restrict__ w_r)
{
    int idx = blockIdx.x*256 + threadIdx.x;
    const int NT = DM_*DM_;
    if (idx < 4*NT){
        int mat = idx / NT, e = idx % NT;
        int o = e >> 8, i = e & 255;
        const float* W = (mat==0)?WQ:(mat==1)?WK:(mat==2)?WV:WO;
        g_WT[mat][i*DM_+o] = W[o*DM_+i];
    } else {
        int r = idx - 4*NT;
        if (r < 2*H_*T_*M_){
            int set = r / (H_*T_*M_);
            int q   = r % (H_*T_*M_);
            int h   = q / (T_*M_);
            int q2  = q % (T_*M_);
            int tt  = q2 / M_;
            int m   = q2 % M_;
            int d = m >> 2, k = m & 3;                 // m = d*NK + k
            int src = ((h*DH_+d)*T_+tt)*NK_+k;
            const float* mu = set ? mu_r : mu_a;
            const float* sg = set ? sg_r : sg_a;
            const float* w  = set ? w_r  : w_a;
            float s = sg[src];
            float A = -1.4426950408889634f / (2.0f*s*s);   // exp(-d^2/2s^2)=2^(A*d^2)
            float* dst = set ? g_relP : g_absP;
            int o4 = ((h*T_+tt)*M_+m)*4;
            dst[o4+0] = mu[src];
            dst[o4+1] = A;
            dst[o4+2] = w[src];
            dst[o4+3] = 0.f;
        }
    }
}

// ---------------- QKV projection (head layout) --------------------------------
__global__ void qkv_kernel(const float* __restrict__ x)
{
    int row0 = blockIdx.x * 4;                 // [0,512)
    int b = row0 >> 8, l0 = row0 & 255;
    __shared__ float xs[4][DM_];
    int tid = threadIdx.x;
    #pragma unroll
    for (int r=0;r<4;r++) xs[r][tid] = x[(row0+r)*DM_ + tid];
    __syncthreads();
    int o = tid;
    float aQ[4]={0,0,0,0}, aK[4]={0,0,0,0}, aV[4]={0,0,0,0};
    for (int k=0;k<DM_;k++){
        float wq = g_WT[0][k*DM_+o];
        float wk = g_WT[1][k*DM_+o];
        float wv = g_WT[2][k*DM_+o];
        #pragma unroll
        for (int r=0;r<4;r++){
            float xv = xs[r][k];
            aQ[r] = fmaf(xv,wq,aQ[r]);
            aK[r] = fmaf(xv,wk,aK[r]);
            aV[r] = fmaf(xv,wv,aV[r]);
        }
    }
    int h = o >> 5, d = o & 31;
    #pragma unroll
    for (int r=0;r<4;r++){
        int l = l0 + r;
        int idx = ((b*H_+h)*L_+l)*DH_ + d;
        g_Q[idx]=aQ[r]; g_K[idx]=aK[r]; g_V[idx]=aV[r];
    }
}

// ---------------- g_abs -------------------------------------------------------
__global__ void gabs_kernel(const float* __restrict__ tarr)
{
    __shared__ float4 Ps[T_*M_];               // 8KB
    int h = blockIdx.x, b = blockIdx.y;
    int tid = threadIdx.x;
    const float4* gp = (const float4*)g_absP + h*(T_*M_);
    for (int idx=tid; idx<T_*M_; idx+=256) Ps[idx]=gp[idx];
    __syncthreads();
    int p = tid;
    float4 tv = *(const float4*)&tarr[(b*L_+p)*T_];
    float us[4] = {tv.x,tv.y,tv.z,tv.w};
    float acc = 0.f;
    #pragma unroll
    for (int tt=0;tt<T_;tt++){
        float u = us[tt];
        const float4* P = Ps + tt*M_;
        #pragma unroll 4
        for (int m=0;m<M_;m++){
            float4 pr = P[m];
            float d = u - pr.x;
            acc = fmaf(pr.z, ex2f(d*d*pr.y), acc);
        }
    }
    g_gabs[(b*H_+h)*L_+p] = acc * (1.0f/DH_);
}

// ---------------- g_rel (dominant kernel, i<=j symmetry) ----------------------
__global__ void grel_kernel(const float* __restrict__ tarr)
{
    extern __shared__ float4 Ps[];             // H*T*M float4 = 64KB
    int tid = threadIdx.x;
    const float4* gp = (const float4*)g_relP;
    for (int idx=tid; idx<H_*T_*M_; idx+=256) Ps[idx]=gp[idx];
    __syncthreads();
    int p = blockIdx.x*256 + tid;
    int b = blockIdx.y;
    if (p >= NPAIR) return;
    // decode triangular (i<=j)
    float disc = sqrtf((float)((2*L_+1)*(2*L_+1) - 8*p));
    int i = (int)((2.0f*L_+1.0f - disc)*0.5f);
    if (i < 0) i = 0; if (i > L_-1) i = L_-1;
    #define TBASE(ii) ((ii)*L_ - ((ii)*((ii)-1))/2)
    while (i+1 <= L_ && TBASE(i+1) <= p) ++i;
    while (TBASE(i) > p) --i;
    int j = i + (p - TBASE(i));
    #undef TBASE

    float4 ti = *(const float4*)&tarr[(b*L_+i)*T_];
    float4 tj = *(const float4*)&tarr[(b*L_+j)*T_];
    float us[4] = {fabsf(ti.x-tj.x), fabsf(ti.y-tj.y), fabsf(ti.z-tj.z), fabsf(ti.w-tj.w)};

    for (int h=0; h<H_; h++){
        float acc = 0.f;
        #pragma unroll
        for (int tt=0;tt<T_;tt++){
            float u = us[tt];
            const float4* P = Ps + (h*T_+tt)*M_;
            #pragma unroll 4
            for (int m=0;m<M_;m++){
                float4 pr = P[m];
                float d = u - pr.x;
                acc = fmaf(pr.z, ex2f(d*d*pr.y), acc);
            }
        }
        acc *= (1.0f/DH_);
        g_grel[((b*H_+h)*L_+i)*L_+j] = acc;
        g_grel[((b*H_+h)*L_+j)*L_+i] = acc;
    }
}

// ---------------- fused attention ---------------------------------------------
__global__ void attn_kernel(const float* __restrict__ x,
                            const float* __restrict__ alpha,
                            const float* __restrict__ beta,
                            const float* __restrict__ gamma)
{
    extern __shared__ float sm[];
    float* Ks     = sm;                    // 256*33
    float* Vs     = Ks + L_*33;
    float* Xs     = Vs + L_*33;
    float* Qs     = Xs + L_*33;            // 16*32
    float* probs  = Qs + 16*DH_;           // 256
    float* redmax = probs + L_;            // 8
    float* redsum = redmax + 8;            // 8
    float* part   = redsum + 8;            // 256

    int tid = threadIdx.x;
    int i0 = blockIdx.x*16, h = blockIdx.y, b = blockIdx.z;
    const float* Kg = g_K + ((b*H_+h)*L_)*DH_;
    const float* Vg = g_V + ((b*H_+h)*L_)*DH_;
    for (int idx=tid; idx<L_*DH_; idx+=256){
        int r = idx >> 5, c = idx & 31;
        Ks[r*33+c] = Kg[idx];
        Vs[r*33+c] = Vg[idx];
        Xs[r*33+c] = x[(b*L_+r)*DM_ + h*DH_ + c];
    }
    for (int idx=tid; idx<16*DH_; idx+=256)
        Qs[idx] = g_Q[((b*H_+h)*L_ + i0)*DH_ + idx];
    __syncthreads();

    float al2 = 2.0f*alpha[h], be = beta[h], ga = gamma[h];
    int lane = tid & 31, wid = tid >> 5;
    const float invsq = 0.17677669529663687f;  // 1/sqrt(32)

    for (int ii=0; ii<16; ii++){
        int ig = i0 + ii;
        int j = tid;
        float sc = 0.f, pj = 0.f;
        #pragma unroll
        for (int d=0; d<DH_; d++){
            sc = fmaf(Qs[ii*DH_+d], Ks[j*33+d], sc);
            pj = fmaf(Xs[ig*33+d], Xs[j*33+d], pj);
        }
        float grel = g_grel[((b*H_+h)*L_+ig)*L_ + j];
        float gi   = g_gabs[(b*H_+h)*L_+ig];
        float A = fmaf(pj, fmaf(be, grel, al2*gi), ga);
        float s = sc * invsq * A;
        // block max
        float v = s;
        #pragma unroll
        for (int off=16; off; off>>=1) v = fmaxf(v, __shfl_xor_sync(0xffffffffu, v, off));
        if (lane==0) redmax[wid] = v;
        __syncthreads();
        float mx = redmax[0];
        #pragma unroll
        for (int w=1; w<8; w++) mx = fmaxf(mx, redmax[w]);
        float e = __expf(s - mx);
        probs[j] = e;
        float sv = e;
        #pragma unroll
        for (int off=16; off; off>>=1) sv += __shfl_xor_sync(0xffffffffu, sv, off);
        if (lane==0) redsum[wid] = sv;
        __syncthreads();
        float tot = redsum[0];
        #pragma unroll
        for (int w=1; w<8; w++) tot += redsum[w];
        float inv = 1.0f / tot;
        // attn @ V : warp 'wid' handles j-chunk, lane = d
        float pa = 0.f;
        int d = lane, ch = wid;
        #pragma unroll
        for (int q=0; q<32; q++){
            int jj = ch*32 + q;
            pa = fmaf(probs[jj], Vs[jj*33+d], pa);
        }
        part[ch*32+d] = pa;
        __syncthreads();
        if (tid < DH_){
            float o = 0.f;
            #pragma unroll
            for (int c=0;c<8;c++) o += part[c*32+tid];
            g_outh[(b*L_+ig)*DM_ + h*DH_ + tid] = o * inv;
        }
        __syncthreads();
    }
}

// ---------------- output projection -------------------------------------------
__global__ void proj_kernel(const float* __restrict__ bO, float* __restrict__ out)
{
    int row0 = blockIdx.x * 4;
    __shared__ float xs[4][DM_];
    int tid = threadIdx.x;
    #pragma unroll
    for (int r=0;r<4;r++) xs[r][tid] = g_outh[(row0+r)*DM_ + tid];
    __syncthreads();
    int o = tid;
    float acc[4] = {0,0,0,0};
    for (int k=0;k<DM_;k++){
        float w = g_WT[3][k*DM_+o];
        #pragma unroll
        for (int r=0;r<4;r++) acc[r] = fmaf(xs[r][k], w, acc[r]);
    }
    float bb = bO[o];
    #pragma unroll
    for (int r=0;r<4;r++) out[(row0+r)*DM_ + o] = acc[r] + bb;
}

// ---------------- launch -------------------------------------------------------
extern "C" void kernel_launch(void* const* d_in, const int* in_sizes, int n_in,
                              void* d_out, int out_size)
{
    const float* x   = (const float*)d_in[0];
    const float* t   = (const float*)d_in[1];
    const float* WQ  = (const float*)d_in[2];
    const float* WK  = (const float*)d_in[3];
    const float* WV  = (const float*)d_in[4];
    const float* WO  = (const float*)d_in[5];
    const float* bO  = (const float*)d_in[6];
    const float* mua = (const float*)d_in[7];
    const float* sga = (const float*)d_in[8];
    const float* wa  = (const float*)d_in[9];
    const float* mur = (const float*)d_in[10];
    const float* sgr = (const float*)d_in[11];
    const float* wr  = (const float*)d_in[12];
    const float* alpha = (const float*)d_in[13];
    const float* beta  = (const float*)d_in[14];
    const float* gamma = (const float*)d_in[15];

    const int GREL_SMEM = H_*T_*M_*4*sizeof(float);          // 65536
    const int ATTN_SMEM = (3*L_*33 + 16*DH_ + L_ + 16 + L_) * sizeof(float); // 105536
    cudaFuncSetAttribute(grel_kernel, cudaFuncAttributeMaxDynamicSharedMemorySize, GREL_SMEM);
    cudaFuncSetAttribute(attn_kernel, cudaFuncAttributeMaxDynamicSharedMemorySize, ATTN_SMEM);

    int prep_items = 4*DM_*DM_ + 2*H_*T_*M_;
    prep_kernel<<<(prep_items+255)/256, 256>>>(WQ,WK,WV,WO, mua,sga,wa, mur,sgr,wr);
    qkv_kernel<<<(B_*L_)/4, 256>>>(x);
    gabs_kernel<<<dim3(H_,B_), 256>>>(t);
    grel_kernel<<<dim3((NPAIR+255)/256, B_), 256, GREL_SMEM>>>(t);
    attn_kernel<<<dim3(L_/16, H_, B_), 256, ATTN_SMEM>>>(x, alpha, beta, gamma);
    proj_kernel<<<(B_*L_)/4, 256>>>(bO, (float*)d_out);
}

// round 2
// speedup vs baseline: 1.0019x; 1.0019x over previous
#include <cuda_runtime.h>
#include <math.h>

#define B_  2
#define L_  256
#define DM_ 256
#define H_  8
#define DH_ 32
#define T_  4
#define NK_ 4
#define M_  (DH_*NK_)          // 128 gaussian terms per (h,t)
#define NPAIR ((L_*(L_+1))/2)  // 32896 (i<=j pairs)

// ---------------- scratch (device globals; no allocation allowed) -------------
__device__ float g_WT[4][DM_*DM_];          // WQ^T, WK^T, WV^T, WO^T  (1MB)
__device__ float g_Q[B_*H_*L_*DH_];
__device__ float g_K[B_*H_*L_*DH_];
__device__ float g_V[B_*H_*L_*DH_];
__device__ float g_relP[H_*T_*M_*4];        // packed (mu, A, w, 0)
__device__ float g_absP[H_*T_*M_*4];
__device__ float g_gabs[B_*H_*L_];
__device__ float g_grel[B_*H_*L_*L_];       // 4MB
__device__ float g_outh[B_*L_*DM_];

__device__ __forceinline__ float ex2f(float x){
    float r; asm("ex2.approx.ftz.f32 %0, %1;" : "=f"(r) : "f"(x)); return r;
}

// ---------------- prep: transpose W's + pack gaussian params ------------------
__global__ void prep_kernel(const float* __restrict__ WQ, const float* __restrict__ WK,
                            const float* __restrict__ WV, const float* __restrict__ WO,
                            const float* __restrict__ mu_a, const float* __restrict__ sg_a,
                            const float* __restrict__ w_a,
                            const float* __restrict__ mu_r, const float* __restrict__ sg_r,
                            const float* __restrict__ w_r)
{
    int idx = blockIdx.x*256 + threadIdx.x;
    const int NT = DM_*DM_;
    if (idx < 4*NT){
        int mat = idx / NT, e = idx % NT;
        int o = e >> 8, i = e & 255;
        const float* W = (mat==0)?WQ:(mat==1)?WK:(mat==2)?WV:WO;
        g_WT[mat][i*DM_+o] = W[o*DM_+i];
    } else {
        int r = idx - 4*NT;
        if (r < 2*H_*T_*M_){
            int set = r / (H_*T_*M_);
            int q   = r % (H_*T_*M_);
            int h   = q / (T_*M_);
            int q2  = q % (T_*M_);
            int tt  = q2 / M_;
            int m   = q2 % M_;
            int d = m >> 2, k = m & 3;                 // m = d*NK + k
            int src = ((h*DH_+d)*T_+tt)*NK_+k;
            const float* mu = set ? mu_r : mu_a;
            const float* sg = set ? sg_r : sg_a;
            const float* w  = set ? w_r  : w_a;
            float s = sg[src];
            float A = -1.4426950408889634f / (2.0f*s*s);   // exp(-d^2/2s^2)=2^(A*d^2)
            float* dst = set ? g_relP : g_absP;
            int o4 = ((h*T_+tt)*M_+m)*4;
            dst[o4+0] = mu[src];
            dst[o4+1] = A;
            dst[o4+2] = w[src];
            dst[o4+3] = 0.f;
        }
    }
}

// ---------------- QKV projection (head layout) --------------------------------
__global__ void qkv_kernel(const float* __restrict__ x)
{
    int row0 = blockIdx.x * 4;                 // [0,512)
    int b = row0 >> 8, l0 = row0 & 255;
    __shared__ float xs[4][DM_];
    int tid = threadIdx.x;
    #pragma unroll
    for (int r=0;r<4;r++) xs[r][tid] = x[(row0+r)*DM_ + tid];
    __syncthreads();
    int o = tid;
    float aQ[4]={0,0,0,0}, aK[4]={0,0,0,0}, aV[4]={0,0,0,0};
    for (int k=0;k<DM_;k++){
        float wq = g_WT[0][k*DM_+o];
        float wk = g_WT[1][k*DM_+o];
        float wv = g_WT[2][k*DM_+o];
        #pragma unroll
        for (int r=0;r<4;r++){
            float xv = xs[r][k];
            aQ[r] = fmaf(xv,wq,aQ[r]);
            aK[r] = fmaf(xv,wk,aK[r]);
            aV[r] = fmaf(xv,wv,aV[r]);
        }
    }
    int h = o >> 5, d = o & 31;
    #pragma unroll
    for (int r=0;r<4;r++){
        int l = l0 + r;
        int idx = ((b*H_+h)*L_+l)*DH_ + d;
        g_Q[idx]=aQ[r]; g_K[idx]=aK[r]; g_V[idx]=aV[r];
    }
}

// ---------------- g_abs -------------------------------------------------------
__global__ void gabs_kernel(const float* __restrict__ tarr)
{
    __shared__ float4 Ps[T_*M_];               // 8KB
    int h = blockIdx.x, b = blockIdx.y;
    int tid = threadIdx.x;
    const float4* gp = (const float4*)g_absP + h*(T_*M_);
    for (int idx=tid; idx<T_*M_; idx+=256) Ps[idx]=gp[idx];
    __syncthreads();
    int p = tid;
    float4 tv = *(const float4*)&tarr[(b*L_+p)*T_];
    float us[4] = {tv.x,tv.y,tv.z,tv.w};
    float acc = 0.f;
    #pragma unroll
    for (int tt=0;tt<T_;tt++){
        float u = us[tt];
        const float4* P = Ps + tt*M_;
        #pragma unroll 4
        for (int m=0;m<M_;m++){
            float4 pr = P[m];
            float d = u - pr.x;
            acc = fmaf(pr.z, ex2f(d*d*pr.y), acc);
        }
    }
    g_gabs[(b*H_+h)*L_+p] = acc * (1.0f/DH_);
}

// ---------------- g_rel (dominant kernel, i<=j symmetry) ----------------------
__global__ void grel_kernel(const float* __restrict__ tarr)
{
    extern __shared__ float4 Ps[];             // H*T*M float4 = 64KB
    int tid = threadIdx.x;
    const float4* gp = (const float4*)g_relP;
    for (int idx=tid; idx<H_*T_*M_; idx+=256) Ps[idx]=gp[idx];
    __syncthreads();
    int p = blockIdx.x*256 + tid;
    int b = blockIdx.y;
    if (p >= NPAIR) return;
    // decode triangular (i<=j)
    float disc = sqrtf((float)((2*L_+1)*(2*L_+1) - 8*p));
    int i = (int)((2.0f*L_+1.0f - disc)*0.5f);
    if (i < 0) i = 0; if (i > L_-1) i = L_-1;
    #define TBASE(ii) ((ii)*L_ - ((ii)*((ii)-1))/2)
    while (i+1 <= L_ && TBASE(i+1) <= p) ++i;
    while (TBASE(i) > p) --i;
    int j = i + (p - TBASE(i));
    #undef TBASE

    float4 ti = *(const float4*)&tarr[(b*L_+i)*T_];
    float4 tj = *(const float4*)&tarr[(b*L_+j)*T_];
    float us[4] = {fabsf(ti.x-tj.x), fabsf(ti.y-tj.y), fabsf(ti.z-tj.z), fabsf(ti.w-tj.w)};

    for (int h=0; h<H_; h++){
        float acc = 0.f;
        #pragma unroll
        for (int tt=0;tt<T_;tt++){
            float u = us[tt];
            const float4* P = Ps + (h*T_+tt)*M_;
            #pragma unroll 4
            for (int m=0;m<M_;m++){
                float4 pr = P[m];
                float d = u - pr.x;
                acc = fmaf(pr.z, ex2f(d*d*pr.y), acc);
            }
        }
        acc *= (1.0f/DH_);
        g_grel[((b*H_+h)*L_+i)*L_+j] = acc;
        g_grel[((b*H_+h)*L_+j)*L_+i] = acc;
    }
}

// ---------------- fused attention ---------------------------------------------
__global__ void attn_kernel(const float* __restrict__ x,
                            const float* __restrict__ alpha,
                            const float* __restrict__ beta,
                            const float* __restrict__ gamma)
{
    extern __shared__ float sm[];
    float* Ks     = sm;                    // 256*33
    float* Vs     = Ks + L_*33;
    float* Xs     = Vs + L_*33;
    float* Qs     = Xs + L_*33;            // 16*32
    float* probs  = Qs + 16*DH_;           // 256
    float* redmax = probs + L_;            // 8
    float* redsum = redmax + 8;            // 8
    float* part   = redsum + 8;            // 256

    int tid = threadIdx.x;
    int i0 = blockIdx.x*16, h = blockIdx.y, b = blockIdx.z;
    const float* Kg = g_K + ((b*H_+h)*L_)*DH_;
    const float* Vg = g_V + ((b*H_+h)*L_)*DH_;
    for (int idx=tid; idx<L_*DH_; idx+=256){
        int r = idx >> 5, c = idx & 31;
        Ks[r*33+c] = Kg[idx];
        Vs[r*33+c] = Vg[idx];
        Xs[r*33+c] = x[(b*L_+r)*DM_ + h*DH_ + c];
    }
    for (int idx=tid; idx<16*DH_; idx+=256)
        Qs[idx] = g_Q[((b*H_+h)*L_ + i0)*DH_ + idx];
    __syncthreads();

    float al2 = 2.0f*alpha[h], be = beta[h], ga = gamma[h];
    int lane = tid & 31, wid = tid >> 5;
    const float invsq = 0.17677669529663687f;  // 1/sqrt(32)

    for (int ii=0; ii<16; ii++){
        int ig = i0 + ii;
        int j = tid;
        float sc = 0.f, pj = 0.f;
        #pragma unroll
        for (int d=0; d<DH_; d++){
            sc = fmaf(Qs[ii*DH_+d], Ks[j*33+d], sc);
            pj = fmaf(Xs[ig*33+d], Xs[j*33+d], pj);
        }
        float grel = g_grel[((b*H_+h)*L_+ig)*L_ + j];
        float gi   = g_gabs[(b*H_+h)*L_+ig];
        float A = fmaf(pj, fmaf(be, grel, al2*gi), ga);
        float s = sc * invsq * A;
        // block max
        float v = s;
        #pragma unroll
        for (int off=16; off; off>>=1) v = fmaxf(v, __shfl_xor_sync(0xffffffffu, v, off));
        if (lane==0) redmax[wid] = v;
        __syncthreads();
        float mx = redmax[0];
        #pragma unroll
        for (int w=1; w<8; w++) mx = fmaxf(mx, redmax[w]);
        float e = __expf(s - mx);
        probs[j] = e;
        float sv = e;
        #pragma unroll
        for (int off=16; off; off>>=1) sv += __shfl_xor_sync(0xffffffffu, sv, off);
        if (lane==0) redsum[wid] = sv;
        __syncthreads();
        float tot = redsum[0];
        #pragma unroll
        for (int w=1; w<8; w++) tot += redsum[w];
        float inv = 1.0f / tot;
        // attn @ V : warp 'wid' handles j-chunk, lane = d
        float pa = 0.f;
        int d = lane, ch = wid;
        #pragma unroll
        for (int q=0; q<32; q++){
            int jj = ch*32 + q;
            pa = fmaf(probs[jj], Vs[jj*33+d], pa);
        }
        part[ch*32+d] = pa;
        __syncthreads();
        if (tid < DH_){
            float o = 0.f;
            #pragma unroll
            for (int c=0;c<8;c++) o += part[c*32+tid];
            g_outh[(b*L_+ig)*DM_ + h*DH_ + tid] = o * inv;
        }
        __syncthreads();
    }
}

// ---------------- output projection -------------------------------------------
__global__ void proj_kernel(const float* __restrict__ bO, float* __restrict__ out)
{
    int row0 = blockIdx.x * 4;
    __shared__ float xs[4][DM_];
    int tid = threadIdx.x;
    #pragma unroll
    for (int r=0;r<4;r++) xs[r][tid] = g_outh[(row0+r)*DM_ + tid];
    __syncthreads();
    int o = tid;
    float acc[4] = {0,0,0,0};
    for (int k=0;k<DM_;k++){
        float w = g_WT[3][k*DM_+o];
        #pragma unroll
        for (int r=0;r<4;r++) acc[r] = fmaf(xs[r][k], w, acc[r]);
    }
    float bb = bO[o];
    #pragma unroll
    for (int r=0;r<4;r++) out[(row0+r)*DM_ + o] = acc[r] + bb;
}

// ---------------- launch -------------------------------------------------------
extern "C" void kernel_launch(void* const* d_in, const int* in_sizes, int n_in,
                              void* d_out, int out_size)
{
    const float* x   = (const float*)d_in[0];
    const float* t   = (const float*)d_in[1];
    const float* WQ  = (const float*)d_in[2];
    const float* WK  = (const float*)d_in[3];
    const float* WV  = (const float*)d_in[4];
    const float* WO  = (const float*)d_in[5];
    const float* bO  = (const float*)d_in[6];
    const float* mua = (const float*)d_in[7];
    const float* sga = (const float*)d_in[8];
    const float* wa  = (const float*)d_in[9];
    const float* mur = (const float*)d_in[10];
    const float* sgr = (const float*)d_in[11];
    const float* wr  = (const float*)d_in[12];
    const float* alpha = (const float*)d_in[13];
    const float* beta  = (const float*)d_in[14];
    const float* gamma = (const float*)d_in[15];

    const int GREL_SMEM = H_*T_*M_*4*sizeof(float);          // 65536
    const int ATTN_SMEM = (3*L_*33 + 16*DH_ + L_ + 16 + L_) * sizeof(float); // 105536
    cudaFuncSetAttribute(grel_kernel, cudaFuncAttributeMaxDynamicSharedMemorySize, GREL_SMEM);
    cudaFuncSetAttribute(attn_kernel, cudaFuncAttributeMaxDynamicSharedMemorySize, ATTN_SMEM);

    int prep_items = 4*DM_*DM_ + 2*H_*T_*M_;
    prep_kernel<<<(prep_items+255)/256, 256>>>(WQ,WK,WV,WO, mua,sga,wa, mur,sgr,wr);
    qkv_kernel<<<(B_*L_)/4, 256>>>(x);
    gabs_kernel<<<dim3(H_,B_), 256>>>(t);
    grel_kernel<<<dim3((NPAIR+255)/256, B_), 256, GREL_SMEM>>>(t);
    attn_kernel<<<dim3(L_/16, H_, B_), 256, ATTN_SMEM>>>(x, alpha, beta, gamma);
    proj_kernel<<<(B_*L_)/4, 256>>>(bO, (float*)d_out);
}

// round 3
// speedup vs baseline: 1.1440x; 1.1418x over previous
#include <cuda_runtime.h>
#include <math.h>

#define B_  2
#define L_  256
#define DM_ 256
#define H_  8
#define DH_ 32
#define T_  4
#define NK_ 4
#define M_  (DH_*NK_)          // 128 gaussian terms per (h,t)
#define NPAIR ((L_*(L_+1))/2)  // 32896 (i<=j pairs)
#define NTAB 4096
#define TABSZ (NTAB+1)
// narrow threshold: sigma < 0.02  <=>  A < -log2e/(2*0.02^2)
#define A_TH (-1803.3688f)

// ---------------- scratch (device globals; no allocation allowed) -------------
__device__ float  g_WT[4][DM_*DM_];          // WQ^T, WK^T, WV^T, WO^T
__device__ float  g_Q[B_*H_*L_*DH_];
__device__ float  g_K[B_*H_*L_*DH_];
__device__ float  g_V[B_*H_*L_*DH_];
__device__ float4 g_relP[H_*T_*M_];          // packed (mu, A, w, 0)
__device__ float4 g_absP[H_*T_*M_];
__device__ float4 g_nwP[H_*T_*M_];           // narrow (exact) rel terms, compact per (h,t)
__device__ float4 g_wdP[H_*T_*M_];           // wide (tabulated) rel terms, compact per (h,t)
__device__ int    g_ncnt[H_*T_];
__device__ int    g_wcnt[H_*T_];
__device__ float  g_tab[H_*T_*TABSZ];        // per (h,t): sum of wide terms over u grid
__device__ float  g_gabs[B_*H_*L_];
__device__ float  g_grel[B_*H_*L_*L_];
__device__ float  g_outh[B_*L_*DM_];

__device__ __forceinline__ float ex2f(float x){
    float r; asm("ex2.approx.ftz.f32 %0, %1;" : "=f"(r) : "f"(x)); return r;
}

// ---------------- tiled transpose of the 4 weight matrices --------------------
__global__ void transposeW_kernel(const float* __restrict__ WQ, const float* __restrict__ WK,
                                  const float* __restrict__ WV, const float* __restrict__ WO)
{
    __shared__ float tile[32][33];
    int mat = blockIdx.z;
    const float* W = (mat==0)?WQ:(mat==1)?WK:(mat==2)?WV:WO;
    int x0 = blockIdx.x*32, y0 = blockIdx.y*32;
    int tx = threadIdx.x, ty = threadIdx.y;     // 32 x 8
    #pragma unroll
    for (int r=0;r<4;r++)
        tile[ty + r*8][tx] = W[(y0+ty+r*8)*DM_ + x0+tx];
    __syncthreads();
    #pragma unroll
    for (int r=0;r<4;r++)
        g_WT[mat][(x0+ty+r*8)*DM_ + y0+tx] = tile[tx][ty+r*8];
}

// ---------------- pack gaussian params ----------------------------------------
__global__ void pack_kernel(const float* __restrict__ mu_a, const float* __restrict__ sg_a,
                            const float* __restrict__ w_a,
                            const float* __restrict__ mu_r, const float* __restrict__ sg_r,
                            const float* __restrict__ w_r)
{
    int idx = blockIdx.x*256 + threadIdx.x;     // < 2*H*T*M = 8192
    if (idx >= 2*H_*T_*M_) return;
    int set = idx / (H_*T_*M_);
    int q   = idx % (H_*T_*M_);
    int h   = q / (T_*M_);
    int q2  = q % (T_*M_);
    int tt  = q2 / M_;
    int m   = q2 % M_;
    int d = m >> 2, k = m & 3;                  // m = d*NK + k
    int src = ((h*DH_+d)*T_+tt)*NK_+k;
    const float* mu = set ? mu_r : mu_a;
    const float* sg = set ? sg_r : sg_a;
    const float* w  = set ? w_r  : w_a;
    float s = sg[src];
    float A = -1.4426950408889634f / (2.0f*s*s);
    float4 v = make_float4(mu[src], A, w[src], 0.f);
    if (set) g_relP[(h*T_+tt)*M_+m] = v;
    else     g_absP[(h*T_+tt)*M_+m] = v;
}

// ---------------- classify rel terms narrow/wide (serial per (h,t)) ------------
__global__ void classify_kernel()
{
    int ht = threadIdx.x;                        // 0..31
    if (ht >= H_*T_) return;
    int nc = 0, wc = 0;
    for (int m=0; m<M_; m++){
        float4 p = g_relP[ht*M_+m];
        if (p.y < A_TH) g_nwP[ht*M_ + nc++] = p;
        else            g_wdP[ht*M_ + wc++] = p;
    }
    g_ncnt[ht] = nc;
    g_wcnt[ht] = wc;
}

// ---------------- build lookup table for wide rel terms ------------------------
__global__ void tab_kernel()
{
    __shared__ float4 P[M_];
    __shared__ int wc_s;
    int ht = blockIdx.x;
    int tid = threadIdx.x;
    if (tid == 0) wc_s = g_wcnt[ht];
    if (tid < M_) P[tid] = g_wdP[ht*M_ + tid];
    __syncthreads();
    int wc = wc_s;
    for (int e = tid; e < TABSZ; e += 256){
        float u = (float)e * (1.0f/NTAB);
        float acc = 0.f;
        for (int m=0; m<wc; m++){
            float4 pr = P[m];
            float d = u - pr.x;
            acc = fmaf(pr.z, ex2f(d*d*pr.y), acc);
        }
        g_tab[ht*TABSZ + e] = acc;
    }
}

// ---------------- QKV projection (8 rows / block) ------------------------------
__global__ void qkv_kernel(const float* __restrict__ x)
{
    int row0 = blockIdx.x * 8;                 // [0,512)
    int b = row0 >> 8, l0 = row0 & 255;
    __shared__ float xs[8][DM_];
    int tid = threadIdx.x;
    #pragma unroll
    for (int r=0;r<8;r++) xs[r][tid] = x[(row0+r)*DM_ + tid];
    __syncthreads();
    int o = tid;
    float aQ[8], aK[8], aV[8];
    #pragma unroll
    for (int r=0;r<8;r++){ aQ[r]=0.f; aK[r]=0.f; aV[r]=0.f; }
    for (int k=0;k<DM_;k++){
        float wq = g_WT[0][k*DM_+o];
        float wk = g_WT[1][k*DM_+o];
        float wv = g_WT[2][k*DM_+o];
        #pragma unroll
        for (int r=0;r<8;r++){
            float xv = xs[r][k];
            aQ[r] = fmaf(xv,wq,aQ[r]);
            aK[r] = fmaf(xv,wk,aK[r]);
            aV[r] = fmaf(xv,wv,aV[r]);
        }
    }
    int h = o >> 5, d = o & 31;
    #pragma unroll
    for (int r=0;r<8;r++){
        int l = l0 + r;
        int idx = ((b*H_+h)*L_+l)*DH_ + d;
        g_Q[idx]=aQ[r]; g_K[idx]=aK[r]; g_V[idx]=aV[r];
    }
}

// ---------------- g_abs (exact, cheap) ------------------------------------------
__global__ void gabs_kernel(const float* __restrict__ tarr)
{
    __shared__ float4 Ps[T_*M_];
    int h = blockIdx.x, b = blockIdx.y;
    int tid = threadIdx.x;
    for (int idx=tid; idx<T_*M_; idx+=256) Ps[idx] = g_absP[h*(T_*M_) + idx];
    __syncthreads();
    int p = tid;
    float4 tv = *(const float4*)&tarr[(b*L_+p)*T_];
    float us[4] = {tv.x,tv.y,tv.z,tv.w};
    float acc = 0.f;
    #pragma unroll
    for (int tt=0;tt<T_;tt++){
        float u = us[tt];
        const float4* P = Ps + tt*M_;
        #pragma unroll 4
        for (int m=0;m<M_;m++){
            float4 pr = P[m];
            float d = u - pr.x;
            acc = fmaf(pr.z, ex2f(d*d*pr.y), acc);
        }
    }
    g_gabs[(b*H_+h)*L_+p] = acc * (1.0f/DH_);
}

// ---------------- g_rel (table lookup + exact narrow terms, i<=j symmetry) ------
__global__ void grel_kernel(const float* __restrict__ tarr)
{
    __shared__ int ncnt_s[H_*T_];
    int tid = threadIdx.x;
    if (tid < H_*T_) ncnt_s[tid] = g_ncnt[tid];
    __syncthreads();

    int p = blockIdx.x*256 + tid;
    int b = blockIdx.y;
    if (p >= NPAIR) return;
    // decode triangular (i<=j)
    float disc = sqrtf((float)((2*L_+1)*(2*L_+1) - 8*p));
    int i = (int)((2.0f*L_+1.0f - disc)*0.5f);
    if (i < 0) i = 0; if (i > L_-1) i = L_-1;
    #define TBASE(ii) ((ii)*L_ - ((ii)*((ii)-1))/2)
    while (i+1 <= L_ && TBASE(i+1) <= p) ++i;
    while (TBASE(i) > p) --i;
    int j = i + (p - TBASE(i));
    #undef TBASE

    float4 ti = *(const float4*)&tarr[(b*L_+i)*T_];
    float4 tj = *(const float4*)&tarr[(b*L_+j)*T_];
    float us[4] = {fabsf(ti.x-tj.x), fabsf(ti.y-tj.y), fabsf(ti.z-tj.z), fabsf(ti.w-tj.w)};

    int   ib[4]; float fr[4];
    #pragma unroll
    for (int tt=0;tt<4;tt++){
        float f = us[tt] * (float)NTAB;
        int ii2 = (int)f;
        if (ii2 > NTAB-1) ii2 = NTAB-1;
        ib[tt] = ii2;
        fr[tt] = f - (float)ii2;
    }

    for (int h=0; h<H_; h++){
        float acc = 0.f;
        #pragma unroll
        for (int tt=0;tt<4;tt++){
            const float* tb = g_tab + (h*T_+tt)*TABSZ + ib[tt];
            float v0 = __ldg(tb);
            float v1 = __ldg(tb+1);
            acc += fmaf(fr[tt], v1 - v0, v0);
        }
        #pragma unroll
        for (int tt=0;tt<4;tt++){
            int c = ncnt_s[h*T_+tt];
            const float4* np = g_nwP + (h*T_+tt)*M_;
            for (int m=0; m<c; m++){
                float4 pr = np[m];
                float d = us[tt] - pr.x;
                acc = fmaf(pr.z, ex2f(d*d*pr.y), acc);
            }
        }
        acc *= (1.0f/DH_);
        g_grel[((b*H_+h)*L_+i)*L_+j] = acc;
        g_grel[((b*H_+h)*L_+j)*L_+i] = acc;
    }
}

// ---------------- fused attention (32 rows/block, register-tiled) ---------------
#define KTS 260                                  // Kt/Xt row stride (4-aligned, conflict-free)
__global__ __launch_bounds__(256,1) void attn_kernel(const float* __restrict__ x,
                            const float* __restrict__ alpha,
                            const float* __restrict__ beta,
                            const float* __restrict__ gamma)
{
    extern __shared__ float sm[];
    float* Kt     = sm;                    // [32][KTS]  d-major
    float* Xt     = Kt + DH_*KTS;          // [32][KTS]  d-major
    float* Vs     = Xt + DH_*KTS;          // [256][33]  j-major
    float* Qt     = Vs + L_*33;            // [32][32]   d-major (Qt[d][r])
    float* probs  = Qt + DH_*32;           // [32][256]
    float* rowinv = probs + 32*L_;         // [32]

    int tid = threadIdx.x;
    int i0 = blockIdx.x*32, h = blockIdx.y, b = blockIdx.z;
    const float* Kg = g_K + (b*H_+h)*L_*DH_;
    const float* Vg = g_V + (b*H_+h)*L_*DH_;
    const float* Qg = g_Q + ((b*H_+h)*L_ + i0)*DH_;

    for (int idx = tid; idx < L_*DH_; idx += 256){
        int j = idx >> 5, d = idx & 31;
        Kt[d*KTS + j] = Kg[idx];
        Xt[d*KTS + j] = x[(b*L_+j)*DM_ + h*DH_ + d];
        Vs[j*33 + d]  = Vg[idx];
    }
    for (int idx = tid; idx < 32*DH_; idx += 256){
        int r = idx >> 5, d = idx & 31;
        Qt[d*32 + r] = Qg[r*DH_ + d];
    }
    __syncthreads();

    int lane = tid & 31, wid = tid >> 5;
    int rowg = (wid & 3) * 8;                     // this warp's 8 rows (within tile)
    int jb   = (wid >> 2) * 128 + lane*4;         // this thread's 4 cols

    float sc[8][4], pj[8][4];
    #pragma unroll
    for (int r=0;r<8;r++){
        #pragma unroll
        for (int q=0;q<4;q++){ sc[r][q]=0.f; pj[r][q]=0.f; }
    }

    for (int d=0; d<DH_; d++){
        float4 kv = *(const float4*)&Kt[d*KTS + jb];
        float4 xv = *(const float4*)&Xt[d*KTS + jb];
        float4 q0 = *(const float4*)&Qt[d*32 + rowg];
        float4 q1 = *(const float4*)&Qt[d*32 + rowg + 4];
        float4 xi0 = *(const float4*)&Xt[d*KTS + i0 + rowg];
        float4 xi1 = *(const float4*)&Xt[d*KTS + i0 + rowg + 4];
        float qs[8]  = {q0.x,q0.y,q0.z,q0.w,q1.x,q1.y,q1.z,q1.w};
        float xis[8] = {xi0.x,xi0.y,xi0.z,xi0.w,xi1.x,xi1.y,xi1.z,xi1.w};
        float kva[4] = {kv.x,kv.y,kv.z,kv.w};
        float xva[4] = {xv.x,xv.y,xv.z,xv.w};
        #pragma unroll
        for (int r=0;r<8;r++){
            #pragma unroll
            for (int q=0;q<4;q++){
                sc[r][q] = fmaf(qs[r],  kva[q], sc[r][q]);
                pj[r][q] = fmaf(xis[r], xva[q], pj[r][q]);
            }
        }
    }

    float al2 = 2.0f*alpha[h], be = beta[h], ga = gamma[h];
    const float invsq = 0.17677669529663687f;     // 1/sqrt(32)
    #pragma unroll
    for (int r=0;r<8;r++){
        int ig = i0 + rowg + r;
        float gi = g_gabs[(b*H_+h)*L_ + ig];
        float c0 = al2 * gi;
        float4 gr = *(const float4*)&g_grel[((b*H_+h)*L_ + ig)*L_ + jb];
        float4 o;
        o.x = sc[r][0]*invsq*fmaf(pj[r][0], fmaf(be, gr.x, c0), ga);
        o.y = sc[r][1]*invsq*fmaf(pj[r][1], fmaf(be, gr.y, c0), ga);
        o.z = sc[r][2]*invsq*fmaf(pj[r][2], fmaf(be, gr.z, c0), ga);
        o.w = sc[r][3]*invsq*fmaf(pj[r][3], fmaf(be, gr.w, c0), ga);
        *(float4*)&probs[(rowg+r)*L_ + jb] = o;
    }
    __syncthreads();

    // softmax: warp wid handles rows 4*wid .. 4*wid+3
    #pragma unroll
    for (int rr=0; rr<4; rr++){
        int row = wid*4 + rr;
        float v[8]; float mx = -3.402823466e38f;
        #pragma unroll
        for (int k=0;k<8;k++){ v[k] = probs[row*L_ + k*32 + lane]; mx = fmaxf(mx, v[k]); }
        #pragma unroll
        for (int off=16; off; off>>=1) mx = fmaxf(mx, __shfl_xor_sync(0xffffffffu, mx, off));
        float s = 0.f;
        #pragma unroll
        for (int k=0;k<8;k++){ float e = __expf(v[k]-mx); probs[row*L_ + k*32 + lane] = e; s += e; }
        #pragma unroll
        for (int off=16; off; off>>=1) s += __shfl_xor_sync(0xffffffffu, s, off);
        if (lane==0) rowinv[row] = 1.0f/s;
    }
    __syncthreads();

    // attn @ V : warp wid handles rows 4*wid..+3, lane = d, register-blocked
    {
        int base = wid*4;
        float acc[4] = {0.f,0.f,0.f,0.f};
        for (int j=0; j<L_; j+=4){
            float v0 = Vs[(j+0)*33 + lane];
            float v1 = Vs[(j+1)*33 + lane];
            float v2 = Vs[(j+2)*33 + lane];
            float v3 = Vs[(j+3)*33 + lane];
            #pragma unroll
            for (int rr=0; rr<4; rr++){
                float4 pv = *(const float4*)&probs[(base+rr)*L_ + j];
                acc[rr] = fmaf(pv.x, v0, acc[rr]);
                acc[rr] = fmaf(pv.y, v1, acc[rr]);
                acc[rr] = fmaf(pv.z, v2, acc[rr]);
                acc[rr] = fmaf(pv.w, v3, acc[rr]);
            }
        }
        #pragma unroll
        for (int rr=0; rr<4; rr++){
            int row = base + rr;
            g_outh[(b*L_ + i0 + row)*DM_ + h*DH_ + lane] = acc[rr] * rowinv[row];
        }
    }
}

// ---------------- output projection (8 rows / block) ----------------------------
__global__ void proj_kernel(const float* __restrict__ bO, float* __restrict__ out)
{
    int row0 = blockIdx.x * 8;
    __shared__ float xs[8][DM_];
    int tid = threadIdx.x;
    #pragma unroll
    for (int r=0;r<8;r++) xs[r][tid] = g_outh[(row0+r)*DM_ + tid];
    __syncthreads();
    int o = tid;
    float acc[8];
    #pragma unroll
    for (int r=0;r<8;r++) acc[r]=0.f;
    for (int k=0;k<DM_;k++){
        float w = g_WT[3][k*DM_+o];
        #pragma unroll
        for (int r=0;r<8;r++) acc[r] = fmaf(xs[r][k], w, acc[r]);
    }
    float bb = bO[o];
    #pragma unroll
    for (int r=0;r<8;r++) out[(row0+r)*DM_ + o] = acc[r] + bb;
}

// ---------------- launch --------------------------------------------------------
extern "C" void kernel_launch(void* const* d_in, const int* in_sizes, int n_in,
                              void* d_out, int out_size)
{
    const float* x   = (const float*)d_in[0];
    const float* t   = (const float*)d_in[1];
    const float* WQ  = (const float*)d_in[2];
    const float* WK  = (const float*)d_in[3];
    const float* WV  = (const float*)d_in[4];
    const float* WO  = (const float*)d_in[5];
    const float* bO  = (const float*)d_in[6];
    const float* mua = (const float*)d_in[7];
    const float* sga = (const float*)d_in[8];
    const float* wa  = (const float*)d_in[9];
    const float* mur = (const float*)d_in[10];
    const float* sgr = (const float*)d_in[11];
    const float* wr  = (const float*)d_in[12];
    const float* alpha = (const float*)d_in[13];
    const float* beta  = (const float*)d_in[14];
    const float* gamma = (const float*)d_in[15];

    const int ATTN_SMEM = (2*DH_*KTS + L_*33 + DH_*32 + 32*L_ + 32) * sizeof(float);
    static bool attr_done = false;
    if (!attr_done){
        cudaFuncSetAttribute(attn_kernel, cudaFuncAttributeMaxDynamicSharedMemorySize, ATTN_SMEM);
        attr_done = true;
    }

    transposeW_kernel<<<dim3(DM_/32, DM_/32, 4), dim3(32,8)>>>(WQ,WK,WV,WO);
    pack_kernel<<<(2*H_*T_*M_+255)/256, 256>>>(mua,sga,wa, mur,sgr,wr);
    classify_kernel<<<1, 32>>>();
    tab_kernel<<<H_*T_, 256>>>();
    qkv_kernel<<<(B_*L_)/8, 256>>>(x);
    gabs_kernel<<<dim3(H_,B_), 256>>>(t);
    grel_kernel<<<dim3((NPAIR+255)/256, B_), 256>>>(t);
    attn_kernel<<<dim3(L_/32, H_, B_), 256, ATTN_SMEM>>>(x, alpha, beta, gamma);
    proj_kernel<<<(B_*L_)/8, 256>>>(bO, (float*)d_out);
}

// round 4
// speedup vs baseline: 2.0183x; 1.7642x over previous
#include <cuda_runtime.h>
#include <math.h>

#define B_  2
#define L_  256
#define DM_ 256
#define H_  8
#define DH_ 32
#define T_  4
#define NK_ 4
#define M_  (DH_*NK_)          // 128 gaussian terms per (h,t)
#define NPAIR ((L_*(L_+1))/2)  // 32896 (i<=j pairs)
#define NTAB 4096
#define TABSZ (NTAB+1)
// narrow threshold: sigma < 0.02  <=>  A < -log2e/(2*0.02^2)
#define A_TH (-1803.3688f)

// ---------------- scratch (device globals; no allocation allowed) -------------
__device__ float  g_WT[4][DM_*DM_];          // WQ^T, WK^T, WV^T, WO^T
__device__ float  g_Q[B_*H_*L_*DH_];
__device__ float  g_K[B_*H_*L_*DH_];
__device__ float  g_V[B_*H_*L_*DH_];
__device__ float4 g_nwP[H_*T_*M_];           // narrow (exact) rel terms, compact per (h,t)
__device__ int    g_ncnt[H_*T_];
__device__ float  g_tab[H_*T_*TABSZ];        // per (h,t): sum of wide terms over u grid
__device__ float  g_gabs[B_*H_*L_];
__device__ float  g_grel[B_*H_*L_*L_];
__device__ float  g_outh[B_*L_*DM_];

__device__ __forceinline__ float ex2f(float x){
    float r; asm("ex2.approx.ftz.f32 %0, %1;" : "=f"(r) : "f"(x)); return r;
}

// ---------------- tiled transpose of the 4 weight matrices --------------------
__global__ void transposeW_kernel(const float* __restrict__ WQ, const float* __restrict__ WK,
                                  const float* __restrict__ WV, const float* __restrict__ WO)
{
    __shared__ float tile[32][33];
    int mat = blockIdx.z;
    const float* W = (mat==0)?WQ:(mat==1)?WK:(mat==2)?WV:WO;
    int x0 = blockIdx.x*32, y0 = blockIdx.y*32;
    int tx = threadIdx.x, ty = threadIdx.y;     // 32 x 8
    #pragma unroll
    for (int r=0;r<4;r++)
        tile[ty + r*8][tx] = W[(y0+ty+r*8)*DM_ + x0+tx];
    __syncthreads();
    #pragma unroll
    for (int r=0;r<4;r++)
        g_WT[mat][(x0+ty+r*8)*DM_ + y0+tx] = tile[tx][ty+r*8];
}

// ---------------- table build (rel) + narrow compaction + fused gabs ----------
// grid = dim3(18, 32), block = 256
//   x in [0,17): table chunk x for ht=y  (h=y>>2, tt=y&3)
//   x == 17 && y < 16: gabs for h=y>>1, b=y&1
__global__ void tabgabs_kernel(const float* __restrict__ mu_r, const float* __restrict__ sg_r,
                               const float* __restrict__ w_r,
                               const float* __restrict__ mu_a, const float* __restrict__ sg_a,
                               const float* __restrict__ w_a,
                               const float* __restrict__ tarr)
{
    __shared__ float4 Ps[T_*M_];                 // 8KB (gabs uses all, tab uses first 128)
    int tid = threadIdx.x;
    int cx = blockIdx.x, y = blockIdx.y;

    if (cx < 17){
        // ---- table chunk for ht = y ----
        int h = y >> 2, tt = y & 3;
        if (tid < M_){
            int d = tid >> 2, k = tid & 3;
            int src = ((h*DH_+d)*T_+tt)*NK_+k;
            float s = sg_r[src];
            float A = -1.4426950408889634f / (2.0f*s*s);
            Ps[tid] = make_float4(mu_r[src], A, w_r[src], 0.f);
        }
        __syncthreads();
        int e = cx*256 + tid;
        if (e < TABSZ){
            float u = (float)e * (1.0f/NTAB);
            float a0=0.f,a1=0.f,a2=0.f,a3=0.f;
            #pragma unroll 1
            for (int m=0;m<M_;m+=4){
                float4 p0=Ps[m], p1=Ps[m+1], p2=Ps[m+2], p3=Ps[m+3];
                float w0 = (p0.y>=A_TH)?p0.z:0.f;  float d0=u-p0.x;
                float w1 = (p1.y>=A_TH)?p1.z:0.f;  float d1=u-p1.x;
                float w2 = (p2.y>=A_TH)?p2.z:0.f;  float d2=u-p2.x;
                float w3 = (p3.y>=A_TH)?p3.z:0.f;  float d3=u-p3.x;
                a0 = fmaf(w0, ex2f(d0*d0*p0.y), a0);
                a1 = fmaf(w1, ex2f(d1*d1*p1.y), a1);
                a2 = fmaf(w2, ex2f(d2*d2*p2.y), a2);
                a3 = fmaf(w3, ex2f(d3*d3*p3.y), a3);
            }
            g_tab[y*TABSZ + e] = (a0+a1)+(a2+a3);
        }
        // chunk 0: compact narrow terms with warp 0
        if (cx == 0 && tid < 32){
            int base = 0;
            #pragma unroll
            for (int g=0; g<4; g++){
                float4 p = Ps[g*32 + tid];
                bool narrow = (p.y < A_TH);
                unsigned bal = __ballot_sync(0xffffffffu, narrow);
                int pos = __popc(bal & ((1u<<tid)-1u));
                if (narrow) g_nwP[y*M_ + base + pos] = p;
                base += __popc(bal);
            }
            if (tid == 0) g_ncnt[y] = base;
        }
    } else if (y < 16){
        // ---- gabs for (h, b) ----
        int h = y >> 1, b = y & 1;
        for (int pass=0; pass<2; pass++){
            int m2 = pass*256 + tid;             // [0,512)
            int tt = m2 >> 7, m = m2 & 127;
            int d = m >> 2, k = m & 3;
            int src = ((h*DH_+d)*T_+tt)*NK_+k;
            float s = sg_a[src];
            float A = -1.4426950408889634f / (2.0f*s*s);
            Ps[m2] = make_float4(mu_a[src], A, w_a[src], 0.f);
        }
        __syncthreads();
        int p = tid;
        float4 tv = *(const float4*)&tarr[(b*L_+p)*T_];
        float us[4] = {tv.x,tv.y,tv.z,tv.w};
        float acc = 0.f;
        #pragma unroll
        for (int tt=0;tt<T_;tt++){
            float u = us[tt];
            const float4* P = Ps + tt*M_;
            #pragma unroll 4
            for (int m=0;m<M_;m++){
                float4 pr = P[m];
                float d = u - pr.x;
                acc = fmaf(pr.z, ex2f(d*d*pr.y), acc);
            }
        }
        g_gabs[(b*H_+h)*L_+p] = acc * (1.0f/DH_);
    }
}

// ---------------- QKV projection (8 rows / block, one matrix per z) -----------
__global__ void qkv_kernel(const float* __restrict__ x)
{
    int mat = blockIdx.y;                      // 0=Q,1=K,2=V
    int row0 = blockIdx.x * 8;                 // [0,512)
    int b = row0 >> 8, l0 = row0 & 255;
    __shared__ float xs[8][DM_];
    int tid = threadIdx.x;
    #pragma unroll
    for (int r=0;r<8;r++) xs[r][tid] = x[(row0+r)*DM_ + tid];
    __syncthreads();
    int o = tid;
    float acc[8];
    #pragma unroll
    for (int r=0;r<8;r++) acc[r]=0.f;
    const float* W = g_WT[mat];
    for (int k=0;k<DM_;k++){
        float w = W[k*DM_+o];
        #pragma unroll
        for (int r=0;r<8;r++) acc[r] = fmaf(xs[r][k], w, acc[r]);
    }
    float* dst = (mat==0)?g_Q:(mat==1)?g_K:g_V;
    int h = o >> 5, d = o & 31;
    #pragma unroll
    for (int r=0;r<8;r++){
        int l = l0 + r;
        dst[((b*H_+h)*L_+l)*DH_ + d] = acc[r];
    }
}

// ---------------- g_rel (table lookup + exact narrow terms, i<=j symmetry) ----
__global__ void grel_kernel(const float* __restrict__ tarr)
{
    __shared__ int ncnt_s[H_*T_];
    int tid = threadIdx.x;
    if (tid < H_*T_) ncnt_s[tid] = g_ncnt[tid];
    __syncthreads();

    int p = blockIdx.x*256 + tid;
    int b = blockIdx.y;
    if (p >= NPAIR) return;
    // decode triangular (i<=j)
    float disc = sqrtf((float)((2*L_+1)*(2*L_+1) - 8*p));
    int i = (int)((2.0f*L_+1.0f - disc)*0.5f);
    if (i < 0) i = 0; if (i > L_-1) i = L_-1;
    #define TBASE(ii) ((ii)*L_ - ((ii)*((ii)-1))/2)
    while (i+1 <= L_ && TBASE(i+1) <= p) ++i;
    while (TBASE(i) > p) --i;
    int j = i + (p - TBASE(i));
    #undef TBASE

    float4 ti = *(const float4*)&tarr[(b*L_+i)*T_];
    float4 tj = *(const float4*)&tarr[(b*L_+j)*T_];
    float us[4] = {fabsf(ti.x-tj.x), fabsf(ti.y-tj.y), fabsf(ti.z-tj.z), fabsf(ti.w-tj.w)};

    int   ib[4]; float fr[4];
    #pragma unroll
    for (int tt=0;tt<4;tt++){
        float f = us[tt] * (float)NTAB;
        int ii2 = (int)f;
        if (ii2 > NTAB-1) ii2 = NTAB-1;
        ib[tt] = ii2;
        fr[tt] = f - (float)ii2;
    }

    for (int h=0; h<H_; h++){
        float acc = 0.f;
        #pragma unroll
        for (int tt=0;tt<4;tt++){
            const float* tb = g_tab + (h*T_+tt)*TABSZ + ib[tt];
            float v0 = __ldg(tb);
            float v1 = __ldg(tb+1);
            acc += fmaf(fr[tt], v1 - v0, v0);
        }
        #pragma unroll
        for (int tt=0;tt<4;tt++){
            int c = ncnt_s[h*T_+tt];
            const float4* np = g_nwP + (h*T_+tt)*M_;
            for (int m=0; m<c; m++){
                float4 pr = np[m];
                float d = us[tt] - pr.x;
                acc = fmaf(pr.z, ex2f(d*d*pr.y), acc);
            }
        }
        acc *= (1.0f/DH_);
        g_grel[((b*H_+h)*L_+i)*L_+j] = acc;
        g_grel[((b*H_+h)*L_+j)*L_+i] = acc;
    }
}

// ---------------- fused attention (32 rows/block, 512 threads) ----------------
#define KTS 260                                  // Kt/Xt row stride
__global__ __launch_bounds__(512,1) void attn_kernel(const float* __restrict__ x,
                            const float* __restrict__ alpha,
                            const float* __restrict__ beta,
                            const float* __restrict__ gamma)
{
    extern __shared__ float sm[];
    float* Kt     = sm;                    // [32][KTS]  d-major
    float* Xt     = Kt + DH_*KTS;          // [32][KTS]  d-major
    float* Vs     = Xt + DH_*KTS;          // [256][32]  j-major
    float* Qt     = Vs + L_*32;            // [32][32]   d-major (Qt[d][r])
    float* probs  = Qt + DH_*32;           // [32][256]
    float* rowinv = probs + 32*L_;         // [32]

    int tid = threadIdx.x;
    int i0 = blockIdx.x*32, h = blockIdx.y, b = blockIdx.z;
    const float* Kg = g_K + (b*H_+h)*L_*DH_;
    const float* Vg = g_V + (b*H_+h)*L_*DH_;
    const float* Qg = g_Q + ((b*H_+h)*L_ + i0)*DH_;

    for (int idx = tid; idx < L_*DH_; idx += 512){
        int j = idx >> 5, d = idx & 31;
        Kt[d*KTS + j] = Kg[idx];
        Xt[d*KTS + j] = x[(b*L_+j)*DM_ + h*DH_ + d];
        Vs[j*32 + d]  = Vg[idx];
    }
    for (int idx = tid; idx < 32*DH_; idx += 512){
        int r = idx >> 5, d = idx & 31;
        Qt[d*32 + r] = Qg[r*DH_ + d];
    }
    __syncthreads();

    int lane = tid & 31, wid = tid >> 5;
    int r0 = (wid & 7) * 4;                       // this warp's 4 rows
    int jb = (wid >> 3) * 128 + lane*4;           // this thread's 4 cols

    float sc[4][4], pj[4][4];
    #pragma unroll
    for (int r=0;r<4;r++){
        #pragma unroll
        for (int q=0;q<4;q++){ sc[r][q]=0.f; pj[r][q]=0.f; }
    }

    for (int d=0; d<DH_; d++){
        float4 kv  = *(const float4*)&Kt[d*KTS + jb];
        float4 xv  = *(const float4*)&Xt[d*KTS + jb];
        float4 q4  = *(const float4*)&Qt[d*32 + r0];
        float4 xi4 = *(const float4*)&Xt[d*KTS + i0 + r0];
        float qs[4]  = {q4.x,q4.y,q4.z,q4.w};
        float xis[4] = {xi4.x,xi4.y,xi4.z,xi4.w};
        float kva[4] = {kv.x,kv.y,kv.z,kv.w};
        float xva[4] = {xv.x,xv.y,xv.z,xv.w};
        #pragma unroll
        for (int r=0;r<4;r++){
            #pragma unroll
            for (int q=0;q<4;q++){
                sc[r][q] = fmaf(qs[r],  kva[q], sc[r][q]);
                pj[r][q] = fmaf(xis[r], xva[q], pj[r][q]);
            }
        }
    }

    float al2 = 2.0f*alpha[h], be = beta[h], ga = gamma[h];
    const float invsq = 0.17677669529663687f;     // 1/sqrt(32)
    #pragma unroll
    for (int r=0;r<4;r++){
        int ig = i0 + r0 + r;
        float gi = g_gabs[(b*H_+h)*L_ + ig];
        float c0 = al2 * gi;
        float4 gr = *(const float4*)&g_grel[((b*H_+h)*L_ + ig)*L_ + jb];
        float4 o;
        o.x = sc[r][0]*invsq*fmaf(pj[r][0], fmaf(be, gr.x, c0), ga);
        o.y = sc[r][1]*invsq*fmaf(pj[r][1], fmaf(be, gr.y, c0), ga);
        o.z = sc[r][2]*invsq*fmaf(pj[r][2], fmaf(be, gr.z, c0), ga);
        o.w = sc[r][3]*invsq*fmaf(pj[r][3], fmaf(be, gr.w, c0), ga);
        *(float4*)&probs[(r0+r)*L_ + jb] = o;
    }
    __syncthreads();

    // softmax: warp wid handles rows 2*wid, 2*wid+1
    #pragma unroll
    for (int rr=0; rr<2; rr++){
        int row = wid*2 + rr;
        float v[8]; float mx = -3.402823466e38f;
        #pragma unroll
        for (int k=0;k<8;k++){ v[k] = probs[row*L_ + k*32 + lane]; mx = fmaxf(mx, v[k]); }
        #pragma unroll
        for (int off=16; off; off>>=1) mx = fmaxf(mx, __shfl_xor_sync(0xffffffffu, mx, off));
        float s = 0.f;
        #pragma unroll
        for (int k=0;k<8;k++){ float e = __expf(v[k]-mx); probs[row*L_ + k*32 + lane] = e; s += e; }
        #pragma unroll
        for (int off=16; off; off>>=1) s += __shfl_xor_sync(0xffffffffu, s, off);
        if (lane==0) rowinv[row] = 1.0f/s;
    }
    __syncthreads();

    // attn @ V : warp wid handles rows 2*wid, 2*wid+1; lane = d
    {
        int row0r = wid*2;
        float acc0 = 0.f, acc1 = 0.f;
        for (int j=0; j<L_; j+=4){
            float v0 = Vs[(j+0)*32 + lane];
            float v1 = Vs[(j+1)*32 + lane];
            float v2 = Vs[(j+2)*32 + lane];
            float v3 = Vs[(j+3)*32 + lane];
            float4 p0 = *(const float4*)&probs[(row0r+0)*L_ + j];
            float4 p1 = *(const float4*)&probs[(row0r+1)*L_ + j];
            acc0 = fmaf(p0.x, v0, acc0); acc0 = fmaf(p0.y, v1, acc0);
            acc0 = fmaf(p0.z, v2, acc0); acc0 = fmaf(p0.w, v3, acc0);
            acc1 = fmaf(p1.x, v0, acc1); acc1 = fmaf(p1.y, v1, acc1);
            acc1 = fmaf(p1.z, v2, acc1); acc1 = fmaf(p1.w, v3, acc1);
        }
        g_outh[(b*L_ + i0 + row0r+0)*DM_ + h*DH_ + lane] = acc0 * rowinv[row0r+0];
        g_outh[(b*L_ + i0 + row0r+1)*DM_ + h*DH_ + lane] = acc1 * rowinv[row0r+1];
    }
}

// ---------------- output projection (4 rows / block, 128 blocks) ---------------
__global__ void proj_kernel(const float* __restrict__ bO, float* __restrict__ out)
{
    int row0 = blockIdx.x * 4;
    __shared__ float xs[4][DM_];
    int tid = threadIdx.x;
    #pragma unroll
    for (int r=0;r<4;r++) xs[r][tid] = g_outh[(row0+r)*DM_ + tid];
    __syncthreads();
    int o = tid;
    float acc[4];
    #pragma unroll
    for (int r=0;r<4;r++) acc[r]=0.f;
    const float* W = g_WT[3];
    for (int k=0;k<DM_;k++){
        float w = W[k*DM_+o];
        #pragma unroll
        for (int r=0;r<4;r++) acc[r] = fmaf(xs[r][k], w, acc[r]);
    }
    float bb = bO[o];
    #pragma unroll
    for (int r=0;r<4;r++) out[(row0+r)*DM_ + o] = acc[r] + bb;
}

// ---------------- launch --------------------------------------------------------
extern "C" void kernel_launch(void* const* d_in, const int* in_sizes, int n_in,
                              void* d_out, int out_size)
{
    const float* x   = (const float*)d_in[0];
    const float* t   = (const float*)d_in[1];
    const float* WQ  = (const float*)d_in[2];
    const float* WK  = (const float*)d_in[3];
    const float* WV  = (const float*)d_in[4];
    const float* WO  = (const float*)d_in[5];
    const float* bO  = (const float*)d_in[6];
    const float* mua = (const float*)d_in[7];
    const float* sga = (const float*)d_in[8];
    const float* wa  = (const float*)d_in[9];
    const float* mur = (const float*)d_in[10];
    const float* sgr = (const float*)d_in[11];
    const float* wr  = (const float*)d_in[12];
    const float* alpha = (const float*)d_in[13];
    const float* beta  = (const float*)d_in[14];
    const float* gamma = (const float*)d_in[15];

    const int ATTN_SMEM = (2*DH_*KTS + L_*32 + DH_*32 + 32*L_ + 32) * sizeof(float);
    static bool attr_done = false;
    if (!attr_done){
        cudaFuncSetAttribute(attn_kernel, cudaFuncAttributeMaxDynamicSharedMemorySize, ATTN_SMEM);
        attr_done = true;
    }

    transposeW_kernel<<<dim3(DM_/32, DM_/32, 4), dim3(32,8)>>>(WQ,WK,WV,WO);
    tabgabs_kernel<<<dim3(18, 32), 256>>>(mur,sgr,wr, mua,sga,wa, t);
    qkv_kernel<<<dim3((B_*L_)/8, 3), 256>>>(x);
    grel_kernel<<<dim3((NPAIR+255)/256, B_), 256>>>(t);
    attn_kernel<<<dim3(L_/32, H_, B_), 512, ATTN_SMEM>>>(x, alpha, beta, gamma);
    proj_kernel<<<(B_*L_)/4, 256>>>(bO, (float*)d_out);
}

// round 5
// speedup vs baseline: 2.6433x; 1.3097x over previous
#include <cuda_runtime.h>
#include <math.h>

#define B_  2
#define L_  256
#define DM_ 256
#define H_  8
#define DH_ 32
#define T_  4
#define NK_ 4
#define M_  128                 // gaussian terms per (h,t)
#define NPAIR 32896             // L*(L+1)/2, i<=j pairs
#define NTAB 2048
// narrow threshold: sigma < 0.02  <=>  A < -log2e/(2*0.02^2)
#define A_TH (-1803.3688f)
#define KTS 260                 // Kt/Xt row stride

// ---------------- scratch (device globals; no allocation allowed) -------------
__device__ float  g_WT[4][DM_*DM_];
__device__ float  g_Q[B_*H_*L_*DH_];
__device__ float  g_K[B_*H_*L_*DH_];
__device__ float  g_V[B_*H_*L_*DH_];
__device__ float4 g_nwP[H_*T_*M_];           // narrow (exact) rel terms, compact per (h,t)
__device__ int    g_ncnt[H_*T_];
__device__ float2 g_tab2[H_*T_*NTAB];        // (f(e), f(e+1)) pairs
__device__ float  g_gabs[B_*H_*L_];
__device__ float  g_grel[B_*H_*L_*L_];
__device__ float  g_outh[B_*L_*DM_];

__device__ __forceinline__ float ex2f(float x){
    float r; asm("ex2.approx.ftz.f32 %0, %1;" : "=f"(r) : "f"(x)); return r;
}

// ================= prep: transpose | table build | gabs ========================
// bx <  256 : W transpose (mat = bx>>6)
// bx <  512 : rel-table chunk (idx=bx-256: cx=idx&7, ht=idx>>3) + narrow compaction
// bx <  528 : gabs (y=bx-512: h=y>>1, b=y&1)
__global__ void prep_kernel(const float* __restrict__ WQ, const float* __restrict__ WK,
                            const float* __restrict__ WV, const float* __restrict__ WO,
                            const float* __restrict__ mu_r, const float* __restrict__ sg_r,
                            const float* __restrict__ w_r,
                            const float* __restrict__ mu_a, const float* __restrict__ sg_a,
                            const float* __restrict__ w_a,
                            const float* __restrict__ tarr)
{
    __shared__ __align__(16) float sm[2080];
    int bx = blockIdx.x, tid = threadIdx.x;

    if (bx < 256){
        // ---- tiled transpose ----
        float (*tile)[33] = (float(*)[33])sm;
        int mat = bx >> 6, rem = bx & 63;
        int x0 = (rem & 7)*32, y0 = (rem >> 3)*32;
        int tx = tid & 31, ty = tid >> 5;           // 32 x 8
        const float* W = (mat==0)?WQ:(mat==1)?WK:(mat==2)?WV:WO;
        #pragma unroll
        for (int r=0;r<4;r++) tile[ty+r*8][tx] = W[(y0+ty+r*8)*DM_ + x0+tx];
        __syncthreads();
        #pragma unroll
        for (int r=0;r<4;r++) g_WT[mat][(x0+ty+r*8)*DM_ + y0+tx] = tile[tx][ty+r*8];
    } else if (bx < 512){
        // ---- rel table chunk ----
        int idx = bx - 256, cx = idx & 7, y = idx >> 3;   // y = h*T+tt
        int h = y >> 2, tt = y & 3;
        float4* Ps = (float4*)sm;                   // 128 float4
        float*  sv = sm + 512;                      // 257 floats
        if (tid < M_){
            int d = tid >> 2, k = tid & 3;
            int src = ((h*DH_+d)*T_+tt)*NK_+k;
            float s = sg_r[src];
            float A = -1.4426950408889634f / (2.0f*s*s);
            Ps[tid] = make_float4(mu_r[src], A, w_r[src], 0.f);
        }
        __syncthreads();
        int e0 = cx*256;
        for (int ee = tid; ee < 257; ee += 256){
            float u = (float)(e0+ee) * (1.0f/NTAB);
            float a0=0.f,a1=0.f,a2=0.f,a3=0.f;
            #pragma unroll 1
            for (int m=0;m<M_;m+=4){
                float4 p0=Ps[m],p1=Ps[m+1],p2=Ps[m+2],p3=Ps[m+3];
                float w0=(p0.y>=A_TH)?p0.z:0.f; float d0=u-p0.x;
                float w1=(p1.y>=A_TH)?p1.z:0.f; float d1=u-p1.x;
                float w2=(p2.y>=A_TH)?p2.z:0.f; float d2=u-p2.x;
                float w3=(p3.y>=A_TH)?p3.z:0.f; float d3=u-p3.x;
                a0 = fmaf(w0, ex2f(d0*d0*p0.y), a0);
                a1 = fmaf(w1, ex2f(d1*d1*p1.y), a1);
                a2 = fmaf(w2, ex2f(d2*d2*p2.y), a2);
                a3 = fmaf(w3, ex2f(d3*d3*p3.y), a3);
            }
            sv[ee] = (a0+a1)+(a2+a3);
        }
        __syncthreads();
        if (e0 + tid < NTAB)
            g_tab2[y*NTAB + e0 + tid] = make_float2(sv[tid], sv[tid+1]);
        // chunk 0: compact narrow terms with warp 0
        if (cx == 0 && tid < 32){
            int base = 0;
            #pragma unroll
            for (int g=0; g<4; g++){
                float4 p = Ps[g*32 + tid];
                bool narrow = (p.y < A_TH);
                unsigned bal = __ballot_sync(0xffffffffu, narrow);
                int pos = __popc(bal & ((1u<<tid)-1u));
                if (narrow) g_nwP[y*M_ + base + pos] = p;
                base += __popc(bal);
            }
            if (tid == 0) g_ncnt[y] = base;
        }
    } else {
        // ---- gabs for (h, b) ----
        int y = bx - 512; int h = y >> 1, b = y & 1;
        float4* Ps = (float4*)sm;                   // 512 float4
        for (int pass=0; pass<2; pass++){
            int m2 = pass*256 + tid;
            int tt = m2 >> 7, m = m2 & 127;
            int d = m >> 2, k = m & 3;
            int src = ((h*DH_+d)*T_+tt)*NK_+k;
            float s = sg_a[src];
            float A = -1.4426950408889634f / (2.0f*s*s);
            Ps[m2] = make_float4(mu_a[src], A, w_a[src], 0.f);
        }
        __syncthreads();
        int p = tid;
        float4 tv = *(const float4*)&tarr[(b*L_+p)*T_];
        float us[4] = {tv.x,tv.y,tv.z,tv.w};
        float acc = 0.f;
        #pragma unroll
        for (int tt=0;tt<T_;tt++){
            float u = us[tt];
            const float4* P = Ps + tt*M_;
            #pragma unroll 4
            for (int m=0;m<M_;m++){
                float4 pr = P[m];
                float d = u - pr.x;
                acc = fmaf(pr.z, ex2f(d*d*pr.y), acc);
            }
        }
        g_gabs[(b*H_+h)*L_+p] = acc * (1.0f/DH_);
    }
}

// ================= mid: qkv (bx<192) | grel (rest) =============================
__global__ void mid_kernel(const float* __restrict__ x, const float* __restrict__ tarr)
{
    __shared__ __align__(16) float sm2[4096];
    int bx = blockIdx.x, tid = threadIdx.x;

    if (bx < 192){
        // ---- qkv: 16 rows x 128-o-half, one matrix ----
        int mat = bx / 64, rem = bx % 64;
        int rowblk = rem >> 1, ohalf = rem & 1;
        float (*xs)[DM_] = (float(*)[DM_])sm2;      // [16][256]
        int rbase = rowblk*16;
        for (int v = tid; v < 1024; v += 256){
            int r = v >> 6, c4 = (v & 63)*4;
            *(float4*)&xs[r][c4] = *(const float4*)&x[(rbase+r)*DM_ + c4];
        }
        __syncthreads();
        int rsub = tid >> 7, oo = tid & 127;
        int o = ohalf*128 + oo;
        float acc[8];
        #pragma unroll
        for (int r=0;r<8;r++) acc[r]=0.f;
        const float* W = g_WT[mat];
        for (int k=0;k<DM_;k++){
            float w = W[k*DM_+o];
            #pragma unroll
            for (int r=0;r<8;r++) acc[r] = fmaf(xs[rsub*8+r][k], w, acc[r]);
        }
        float* dst = (mat==0)?g_Q:(mat==1)?g_K:g_V;
        int h = o >> 5, d = o & 31;
        #pragma unroll
        for (int r=0;r<8;r++){
            int rg = rbase + rsub*8 + r;
            int b = rg >> 8, l = rg & 255;
            dst[((b*H_+h)*L_+l)*DH_ + d] = acc[r];
        }
    } else {
        // ---- grel: warp = 32 pairs, uniform h ----
        int idx = bx - 192;
        int b  = idx / 1028;
        int pb = idx % 1028;
        int* ncs = (int*)sm2;
        if (tid < 32) ncs[tid] = g_ncnt[tid];
        __syncthreads();

        int p = pb*32 + (tid & 31);                 // < 1028*32 = NPAIR exactly
        int h = tid >> 5;
        // decode triangular (i<=j)
        float disc = sqrtf((float)((2*L_+1)*(2*L_+1) - 8*p));
        int i = (int)((2.0f*L_+1.0f - disc)*0.5f);
        if (i < 0) i = 0; if (i > L_-1) i = L_-1;
        #define TBASE(ii) ((ii)*L_ - ((ii)*((ii)-1))/2)
        while (i+1 <= L_ && TBASE(i+1) <= p) ++i;
        while (TBASE(i) > p) --i;
        int j = i + (p - TBASE(i));
        #undef TBASE

        float4 ti = *(const float4*)&tarr[(b*L_+i)*T_];
        float4 tj = *(const float4*)&tarr[(b*L_+j)*T_];
        float us[4] = {fabsf(ti.x-tj.x), fabsf(ti.y-tj.y), fabsf(ti.z-tj.z), fabsf(ti.w-tj.w)};

        float acc = 0.f;
        #pragma unroll
        for (int tt=0;tt<4;tt++){
            float f = us[tt] * (float)NTAB;
            int ib = (int)f;
            if (ib > NTAB-1) ib = NTAB-1;
            float fr = f - (float)ib;
            float2 v = __ldg(&g_tab2[(h*T_+tt)*NTAB + ib]);
            acc += fmaf(fr, v.y - v.x, v.x);
        }
        #pragma unroll
        for (int tt=0;tt<4;tt++){
            int c = ncs[h*T_+tt];
            const float4* np = g_nwP + (h*T_+tt)*M_;
            for (int m=0; m<c; m++){
                float4 pr = __ldg(&np[m]);
                float d = us[tt] - pr.x;
                acc = fmaf(pr.z, ex2f(d*d*pr.y), acc);
            }
        }
        acc *= (1.0f/DH_);
        g_grel[((b*H_+h)*L_+i)*L_+j] = acc;
        g_grel[((b*H_+h)*L_+j)*L_+i] = acc;
    }
}

// ================= fused attention: 16 rows/block, 256 threads ================
__global__ __launch_bounds__(256,2) void attn_kernel(const float* __restrict__ x,
                            const float* __restrict__ alpha,
                            const float* __restrict__ beta,
                            const float* __restrict__ gamma)
{
    extern __shared__ float sm[];
    float* Kt    = sm;              // [32][KTS]  (phase 1)
    float* Xt    = sm + 8320;       // [32][KTS]
    float* Qt    = sm + 16640;      // [32][16]
    float* Vs    = sm + 17152;      // [256][32]
    float* probs = sm;              // [16][256]  (phase 2, aliases Kt)

    int tid = threadIdx.x;
    int i0 = blockIdx.x*16, h = blockIdx.y, b = blockIdx.z;
    const float4* Kg4 = (const float4*)(g_K + (b*H_+h)*L_*DH_);
    const float4* Vg4 = (const float4*)(g_V + (b*H_+h)*L_*DH_);

    for (int v = tid; v < 2048; v += 256){
        int j = v >> 3, d4 = (v & 7)*4;
        float4 kq = Kg4[v];
        Kt[(d4+0)*KTS+j]=kq.x; Kt[(d4+1)*KTS+j]=kq.y; Kt[(d4+2)*KTS+j]=kq.z; Kt[(d4+3)*KTS+j]=kq.w;
        float4 vv = Vg4[v];
        *(float4*)&Vs[j*DH_ + d4] = vv;
        float4 xv = *(const float4*)&x[(b*L_+j)*DM_ + h*DH_ + d4];
        Xt[(d4+0)*KTS+j]=xv.x; Xt[(d4+1)*KTS+j]=xv.y; Xt[(d4+2)*KTS+j]=xv.z; Xt[(d4+3)*KTS+j]=xv.w;
    }
    if (tid < 128){
        int r = tid >> 3, d4 = (tid & 7)*4;
        float4 q = *(const float4*)&g_Q[((b*H_+h)*L_ + i0 + r)*DH_ + d4];
        Qt[(d4+0)*16+r]=q.x; Qt[(d4+1)*16+r]=q.y; Qt[(d4+2)*16+r]=q.z; Qt[(d4+3)*16+r]=q.w;
    }
    __syncthreads();

    int lane = tid & 31, wid = tid >> 5;
    int r0 = (wid & 3)*4;                          // 4 rows of 16
    int jb = (wid >> 2)*128 + lane*4;              // 4 cols of 256

    float sc[4][4], pj[4][4];
    #pragma unroll
    for (int r=0;r<4;r++){
        #pragma unroll
        for (int q=0;q<4;q++){ sc[r][q]=0.f; pj[r][q]=0.f; }
    }
    for (int d=0; d<DH_; d++){
        float4 kv  = *(const float4*)&Kt[d*KTS + jb];
        float4 xv  = *(const float4*)&Xt[d*KTS + jb];
        float4 q4  = *(const float4*)&Qt[d*16 + r0];
        float4 xi4 = *(const float4*)&Xt[d*KTS + i0 + r0];
        float qs[4]  = {q4.x,q4.y,q4.z,q4.w};
        float xis[4] = {xi4.x,xi4.y,xi4.z,xi4.w};
        float kva[4] = {kv.x,kv.y,kv.z,kv.w};
        float xva[4] = {xv.x,xv.y,xv.z,xv.w};
        #pragma unroll
        for (int r=0;r<4;r++){
            #pragma unroll
            for (int q=0;q<4;q++){
                sc[r][q] = fmaf(qs[r],  kva[q], sc[r][q]);
                pj[r][q] = fmaf(xis[r], xva[q], pj[r][q]);
            }
        }
    }

    float al2 = 2.0f*alpha[h], be = beta[h], ga = gamma[h];
    const float invsq = 0.17677669529663687f;      // 1/sqrt(32)
    float4 ov[4];
    #pragma unroll
    for (int r=0;r<4;r++){
        int ig = i0 + r0 + r;
        float gi = g_gabs[(b*H_+h)*L_ + ig];
        float c0 = al2 * gi;
        float4 gr = *(const float4*)&g_grel[((b*H_+h)*L_ + ig)*L_ + jb];
        ov[r].x = sc[r][0]*invsq*fmaf(pj[r][0], fmaf(be, gr.x, c0), ga);
        ov[r].y = sc[r][1]*invsq*fmaf(pj[r][1], fmaf(be, gr.y, c0), ga);
        ov[r].z = sc[r][2]*invsq*fmaf(pj[r][2], fmaf(be, gr.z, c0), ga);
        ov[r].w = sc[r][3]*invsq*fmaf(pj[r][3], fmaf(be, gr.w, c0), ga);
    }
    __syncthreads();                                // all warps done reading Kt/Xt/Qt
    #pragma unroll
    for (int r=0;r<4;r++) *(float4*)&probs[(r0+r)*L_ + jb] = ov[r];
    __syncthreads();

    // softmax + @V: warp wid owns rows 2*wid, 2*wid+1
    float inv[2];
    #pragma unroll
    for (int rr=0; rr<2; rr++){
        int row = wid*2 + rr;
        float v[8]; float mx = -3.402823466e38f;
        #pragma unroll
        for (int k=0;k<8;k++){ v[k] = probs[row*L_ + k*32 + lane]; mx = fmaxf(mx, v[k]); }
        #pragma unroll
        for (int off=16; off; off>>=1) mx = fmaxf(mx, __shfl_xor_sync(0xffffffffu, mx, off));
        float s = 0.f;
        #pragma unroll
        for (int k=0;k<8;k++){ float e = __expf(v[k]-mx); probs[row*L_ + k*32 + lane] = e; s += e; }
        #pragma unroll
        for (int off=16; off; off>>=1) s += __shfl_xor_sync(0xffffffffu, s, off);
        inv[rr] = 1.0f/s;
    }
    __syncwarp();
    {
        int rbase = wid*2;
        float acc0 = 0.f, acc1 = 0.f;
        for (int j=0; j<L_; j+=4){
            float v0 = Vs[(j+0)*DH_ + lane];
            float v1 = Vs[(j+1)*DH_ + lane];
            float v2 = Vs[(j+2)*DH_ + lane];
            float v3 = Vs[(j+3)*DH_ + lane];
            float4 p0 = *(const float4*)&probs[(rbase+0)*L_ + j];
            float4 p1 = *(const float4*)&probs[(rbase+1)*L_ + j];
            acc0 = fmaf(p0.x, v0, acc0); acc0 = fmaf(p0.y, v1, acc0);
            acc0 = fmaf(p0.z, v2, acc0); acc0 = fmaf(p0.w, v3, acc0);
            acc1 = fmaf(p1.x, v0, acc1); acc1 = fmaf(p1.y, v1, acc1);
            acc1 = fmaf(p1.z, v2, acc1); acc1 = fmaf(p1.w, v3, acc1);
        }
        g_outh[(b*L_ + i0 + rbase+0)*DM_ + h*DH_ + lane] = acc0 * inv[0];
        g_outh[(b*L_ + i0 + rbase+1)*DM_ + h*DH_ + lane] = acc1 * inv[1];
    }
}

// ================= output projection ==========================================
__global__ void proj_kernel(const float* __restrict__ bO, float* __restrict__ out)
{
    int row0 = blockIdx.x * 4;
    __shared__ float xs[4][DM_];
    int tid = threadIdx.x;
    #pragma unroll
    for (int r=0;r<4;r++) xs[r][tid] = g_outh[(row0+r)*DM_ + tid];
    __syncthreads();
    int o = tid;
    float acc[4];
    #pragma unroll
    for (int r=0;r<4;r++) acc[r]=0.f;
    const float* W = g_WT[3];
    for (int k=0;k<DM_;k++){
        float w = W[k*DM_+o];
        #pragma unroll
        for (int r=0;r<4;r++) acc[r] = fmaf(xs[r][k], w, acc[r]);
    }
    float bb = bO[o];
    #pragma unroll
    for (int r=0;r<4;r++) out[(row0+r)*DM_ + o] = acc[r] + bb;
}

// ================= launch =====================================================
extern "C" void kernel_launch(void* const* d_in, const int* in_sizes, int n_in,
                              void* d_out, int out_size)
{
    const float* x   = (const float*)d_in[0];
    const float* t   = (const float*)d_in[1];
    const float* WQ  = (const float*)d_in[2];
    const float* WK  = (const float*)d_in[3];
    const float* WV  = (const float*)d_in[4];
    const float* WO  = (const float*)d_in[5];
    const float* bO  = (const float*)d_in[6];
    const float* mua = (const float*)d_in[7];
    const float* sga = (const float*)d_in[8];
    const float* wa  = (const float*)d_in[9];
    const float* mur = (const float*)d_in[10];
    const float* sgr = (const float*)d_in[11];
    const float* wr  = (const float*)d_in[12];
    const float* alpha = (const float*)d_in[13];
    const float* beta  = (const float*)d_in[14];
    const float* gamma = (const float*)d_in[15];

    const int ATTN_SMEM = 25344 * sizeof(float);   // 101376 B
    static bool attr_done = false;
    if (!attr_done){
        cudaFuncSetAttribute(attn_kernel, cudaFuncAttributeMaxDynamicSharedMemorySize, ATTN_SMEM);
        attr_done = true;
    }

    prep_kernel<<<528, 256>>>(WQ,WK,WV,WO, mur,sgr,wr, mua,sga,wa, t);
    mid_kernel<<<192 + 2*1028, 256>>>(x, t);
    attn_kernel<<<dim3(16, H_, B_), 256, ATTN_SMEM>>>(x, alpha, beta, gamma);
    proj_kernel<<<(B_*L_)/4, 256>>>(bO, (float*)d_out);
}